// round 17
// baseline (speedup 1.0000x reference)
#include <cuda_runtime.h>
#include <cuda_fp16.h>
#include <cstdint>
#include <math.h>

// ---------------- problem constants ----------------
#define B      256
#define T      168
#define F_IN   128
#define H      512
#define H4     2048
#define KENC   640
#define H2     1024
#define NDEC   4096
#define KDEC   1024
#define L_OUT  48

// ---------------- tiling ----------------
#define BM     64
#define BN     128
#define KC     128
#define PADH   136                      // halves; 272B row stride -> ldmatrix conflict-free
#define HSP    33
#define ASTG   (BM * PADH * 2)          // 17408 B per encoder A stage
#define BSTG   (BN * PADH * 2)          // 34816 B per W chunk
#define WOFFE  (3 * ASTG)               // 52224: encoder resident-W region
#define STG_B  ((BM + BN) * PADH * 2)   // 52224 B combined decoder stage
#define BOFF   ((uint32_t)(BM * PADH * 2))
#define HOFFD  (3 * STG_B)              // 156672: decoder Hs buffer (non-aliased)
#define DYNB   (WOFFE + 5 * BSTG)       // 226304 B dynamic smem
#define NCTA   128

// ---------------- device scratch ----------------
__device__ __align__(16) __half g_xT[(size_t)T * B * F_IN];
__device__ __align__(16) __half g_Wenc[2][H4 * KENC];
__device__ __align__(16) float  g_benc[2][H4];
__device__ __align__(16) __half g_Wdec[(size_t)NDEC * KDEC];
__device__ __align__(16) float  g_bdec[NDEC];
__device__ __align__(16) float  g_win[NDEC];
__device__ __align__(16) float  g_fcw[H2];
__device__ __align__(16) __half g_h[2][B * H2];
__device__ __align__(16) float  g_c[B * H2];
__device__ __align__(16) float  g_dpart[L_OUT * 32 * B];

__device__ unsigned g_bcnt[16];
__device__ unsigned g_bgen[16];

// ---------------- helpers (proven exp-based activations) ----------------
__device__ __forceinline__ float fsigm(float x) { return __fdividef(1.0f, 1.0f + __expf(-x)); }
__device__ __forceinline__ float ftanh(float x) { return __fdividef(2.0f, 1.0f + __expf(-2.0f * x)) - 1.0f; }
__device__ __forceinline__ float ldcg(const float* p) {
    float v; asm volatile("ld.global.cg.f32 %0, [%1];" : "=f"(v) : "l"(p)); return v;
}

__device__ __forceinline__ void barrier_grp(int gidx, unsigned n) {
    __syncthreads();
    if (threadIdx.x == 0) {
        unsigned cur, old;
        asm volatile("ld.relaxed.gpu.global.u32 %0, [%1];" : "=r"(cur) : "l"(&g_bgen[gidx]));
        asm volatile("atom.acq_rel.gpu.global.add.u32 %0, [%1], 1;" : "=r"(old) : "l"(&g_bcnt[gidx]));
        if (old == n - 1u) {
            asm volatile("st.relaxed.gpu.global.u32 [%0], %1;" :: "l"(&g_bcnt[gidx]), "r"(0u));
            asm volatile("st.release.gpu.global.u32 [%0], %1;" :: "l"(&g_bgen[gidx]), "r"(cur + 1u));
        } else {
            unsigned v;
            do {
                asm volatile("ld.acquire.gpu.global.u32 %0, [%1];" : "=r"(v) : "l"(&g_bgen[gidx]));
            } while (v == cur);
        }
    }
    __syncthreads();
}

__device__ __forceinline__ void cpa16_ca(uint32_t dst, const __half* src) {
    asm volatile("cp.async.ca.shared.global [%0], [%1], 16;\n" :: "r"(dst), "l"(src));
}
__device__ __forceinline__ void cpa16_cg(uint32_t dst, const __half* src) {
    asm volatile("cp.async.cg.shared.global [%0], [%1], 16;\n" :: "r"(dst), "l"(src));
}
#define CP_COMMIT() asm volatile("cp.async.commit_group;\n" ::: "memory")
#define CP_WAIT1()  asm volatile("cp.async.wait_group 1;\n" ::: "memory")
#define CP_WAIT0()  asm volatile("cp.async.wait_group 0;\n" ::: "memory")

__device__ __forceinline__ void load_A(uint32_t su, const __half* __restrict__ a,
                                       int astride, int tid, int cg) {
#pragma unroll
    for (int i = tid; i < BM * 16; i += 256) {
        int r = i >> 4, v = i & 15;
        uint32_t d = su + (uint32_t)(r * PADH + v * 8) * 2u;
        const __half* s = a + (size_t)r * astride + v * 8;
        if (cg) cpa16_cg(d, s); else cpa16_ca(d, s);
    }
}
__device__ __forceinline__ void load_B(uint32_t su, const __half* __restrict__ b,
                                       int bstride, int tid) {
#pragma unroll
    for (int i = tid; i < BN * 16; i += 256) {
        int r = i >> 4, v = i & 15;
        cpa16_ca(su + (uint32_t)(r * PADH + v * 8) * 2u, b + (size_t)r * bstride + v * 8);
    }
}

// ---------------- ldmatrix + mma ----------------
__device__ __forceinline__ void lm4(uint32_t (&r)[4], uint32_t addr) {
    asm volatile("ldmatrix.sync.aligned.m8n8.x4.shared.b16 {%0,%1,%2,%3}, [%4];"
                 : "=r"(r[0]), "=r"(r[1]), "=r"(r[2]), "=r"(r[3]) : "r"(addr));
}
__device__ __forceinline__ void hmma(float (&d)[4], const uint32_t (&a)[4],
                                     uint32_t b0, uint32_t b1) {
    asm volatile("mma.sync.aligned.m16n8k16.row.col.f32.f16.f16.f32 "
                 "{%0,%1,%2,%3},{%4,%5,%6,%7},{%8,%9},{%0,%1,%2,%3};"
                 : "+f"(d[0]), "+f"(d[1]), "+f"(d[2]), "+f"(d[3])
                 : "r"(a[0]), "r"(a[1]), "r"(a[2]), "r"(a[3]), "r"(b0), "r"(b1));
}
__device__ __forceinline__ void mma_chunk_lm(uint32_t asu, uint32_t bsu,
                                             float (&acc)[2][4][4],
                                             uint32_t bA0, uint32_t bA1,
                                             uint32_t bB0, uint32_t bB1) {
#pragma unroll
    for (int kb = 0; kb < 8; kb++) {
        uint32_t ko = (uint32_t)kb * 32u;
        uint32_t a0[4], a1[4], b0[4], b1[4];
        lm4(a0, asu + ko + bA0);
        lm4(a1, asu + ko + bA1);
        lm4(b0, bsu + ko + bB0);
        lm4(b1, bsu + ko + bB1);
        hmma(acc[0][0], a0, b0[0], b0[2]);
        hmma(acc[0][1], a0, b0[1], b0[3]);
        hmma(acc[0][2], a0, b1[0], b1[2]);
        hmma(acc[0][3], a0, b1[1], b1[3]);
        hmma(acc[1][0], a1, b0[0], b0[2]);
        hmma(acc[1][1], a1, b0[1], b0[3]);
        hmma(acc[1][2], a1, b1[0], b1[2]);
        hmma(acc[1][3], a1, b1[1], b1[3]);
    }
}

// ---------------- prep ----------------
__global__ void prep_misc(const float* __restrict__ x) {
    int i = blockIdx.x * blockDim.x + threadIdx.x;
    if (i < T * B * F_IN) {
        int f = i & 127;
        int r = i >> 7;
        int b = r & 255;
        int t = r >> 8;
        g_xT[i] = __float2half(x[((size_t)b * T + t) * F_IN + f]);
    }
    if (i < B * H2) {
        g_h[0][i] = __half(0.0f);
        g_h[1][i] = __half(0.0f);
        g_c[i]    = 0.0f;
    }
}

#define EW (2 * H4 * KENC)
#define DW (NDEC * KDEC)
#define PREP_TOT (EW + DW + 2 * H4 + NDEC + H2)

__global__ void prep_w(const float* __restrict__ eWih_f, const float* __restrict__ eWhh_f,
                       const float* __restrict__ ebih_f, const float* __restrict__ ebhh_f,
                       const float* __restrict__ eWih_b, const float* __restrict__ eWhh_b,
                       const float* __restrict__ ebih_b, const float* __restrict__ ebhh_b,
                       const float* __restrict__ dWih,   const float* __restrict__ dWhh,
                       const float* __restrict__ dbih,   const float* __restrict__ dbhh,
                       const float* __restrict__ fcW) {
    int i = blockIdx.x * blockDim.x + threadIdx.x;
    if (i >= PREP_TOT) return;

    if (i < EW) {
        int dir = i / (H4 * KENC);
        int r   = i - dir * (H4 * KENC);
        int n   = r / KENC;
        int k   = r - n * KENC;
        int u = n >> 2, gt = n & 3;
        int row = gt * H + u;
        const float* Wih = dir ? eWih_b : eWih_f;
        const float* Whh = dir ? eWhh_b : eWhh_f;
        float v = (k < F_IN) ? Wih[row * F_IN + k] : Whh[row * H + (k - F_IN)];
        g_Wenc[dir][n * KENC + k] = __float2half(v);
    } else if (i < EW + DW) {
        int r = i - EW;
        int n = r / KDEC;
        int k = r - n * KDEC;
        int u = n >> 2, gt = n & 3;
        int row = gt * H2 + u;
        g_Wdec[(size_t)n * KDEC + k] = __float2half(dWhh[(size_t)row * KDEC + k]);
    } else {
        int r = i - EW - DW;
        if (r < 2 * H4) {
            int dir = r >> 11;
            int n = r & (H4 - 1);
            int u = n >> 2, gt = n & 3;
            int row = gt * H + u;
            g_benc[dir][n] = dir ? (ebih_b[row] + ebhh_b[row]) : (ebih_f[row] + ebhh_f[row]);
        } else if (r < 2 * H4 + NDEC) {
            int n = r - 2 * H4;
            int u = n >> 2, gt = n & 3;
            int row = gt * H2 + u;
            g_bdec[n] = dbih[row] + dbhh[row];
            g_win[n]  = dWih[row];
        } else {
            int u = r - 2 * H4 - NDEC;
            g_fcw[u] = fcW[u];
        }
    }
}

// ---------------- persistent kernel ----------------
__global__ __launch_bounds__(256, 1) void persist(float* __restrict__ out,
                                                  const float* __restrict__ fcb) {
    extern __shared__ __align__(16) unsigned char dynraw[];
    float* Hs = reinterpret_cast<float*>(dynraw + HOFFD);   // dec h staging (non-aliased)
    __shared__ float sFc[32];
    __shared__ float predS[BM];
    __shared__ float predP[BM][4];

    uint32_t dynu = (uint32_t)__cvta_generic_to_shared(dynraw);
    int bx = blockIdx.x;
    int tid = threadIdx.x;
    int lane = tid & 31, wid = tid >> 5;
    int wm = wid & 1, wn = wid >> 1;
    int lg = lane >> 2, tg = lane & 3;
    int po = tg & 1;                       // pair parity within (tg, tg^1)
    int la15 = lane & 15, lk = (lane >> 4) << 3;
    float fcb0 = fcb[0];

    uint32_t bA0 = (uint32_t)((wm * 32 + la15) * PADH + lk) * 2u;
    uint32_t bA1 = bA0 + 16u * PADH * 2u;
    uint32_t bB0 = (uint32_t)((wn * 32 + la15) * PADH + lk) * 2u;
    uint32_t bB1 = bB0 + 16u * PADH * 2u;

    int uL[4];
#pragma unroll
    for (int ni = 0; ni < 4; ni++) uL[ni] = wn * 8 + ni * 2 + (tg >> 1);

    float cR[8];
    float bI[4], bF[4], bG[4], bO[4];

    // =============== encoder (resident W, register epilogue) ===============
    {
        int dir = bx >> 6;
        int mt  = (bx >> 4) & 3;
        int nt  = bx & 15;
        int gid = bx >> 4;                 // 8 groups of 16 CTAs sharing (dir, mt)
        int m0 = mt * BM, n0 = nt * BN;
        const __half* W = g_Wenc[dir] + (size_t)n0 * KENC;

        // prologue: resident W chunks (5 groups), then X(0) (1 group)
#pragma unroll
        for (int c = 0; c < 5; c++) {
            load_B(dynu + (uint32_t)(WOFFE + c * BSTG), W + c * KC, KENC, tid);
            CP_COMMIT();
        }
        {
            int tt0 = dir ? (T - 1) : 0;
            load_A(dynu, g_xT + ((size_t)tt0 * B + m0) * F_IN, F_IN, tid, 0);
            CP_COMMIT();
        }
        // per-thread gate biases
#pragma unroll
        for (int ni = 0; ni < 4; ni++) {
            const float* bp = g_benc[dir] + n0 + 4 * uL[ni];
            bI[ni] = bp[0]; bF[ni] = bp[1]; bG[ni] = bp[2]; bO[ni] = bp[3];
        }
#pragma unroll
        for (int i = 0; i < 8; i++) cR[i] = 0.0f;

        for (int t = 0; t < T; t++) {
            int p = t & 1;
            const __half* hb = g_h[p] + (size_t)m0 * H2 + dir * H;
            __half* hout = g_h[p ^ 1];

            load_A(dynu + 1u * ASTG, hb, H2, tid, 1);   // A1 (h cols 0-127)
            CP_COMMIT();

            float acc[2][4][4];
#pragma unroll
            for (int a = 0; a < 2; a++)
#pragma unroll
                for (int bq = 0; bq < 4; bq++)
#pragma unroll
                    for (int cq = 0; cq < 4; cq++) acc[a][bq][cq] = 0.0f;

#pragma unroll
            for (int ch = 0; ch < 5; ch++) {
                if (ch == 4) { CP_WAIT0(); } else { CP_WAIT1(); }
                __syncthreads();
                if (ch == 0) {
                    load_A(dynu + 2u * ASTG, hb + 128, H2, tid, 1);   // A2 -> st2
                } else if (ch == 1) {
                    load_A(dynu + 0u * ASTG, hb + 256, H2, tid, 1);   // A3 -> st0
                } else if (ch == 2) {
                    load_A(dynu + 1u * ASTG, hb + 384, H2, tid, 1);   // A4 -> st1
                } else if (ch == 4 && t + 1 < T) {
                    int tt2 = dir ? (T - 2 - t) : (t + 1);
                    load_A(dynu, g_xT + ((size_t)tt2 * B + m0) * F_IN, F_IN, tid, 0); // X(t+1) -> st0
                }
                CP_COMMIT();   // uniform: one group per slot (empty allowed)
                mma_chunk_lm(dynu + (uint32_t)((ch % 3) * ASTG),
                             dynu + (uint32_t)(WOFFE + ch * BSTG),
                             acc, bA0, bA1, bB0, bB1);
            }

            // register epilogue: pair-exchange via shfl, cell update, h -> gmem
#pragma unroll
            for (int mi = 0; mi < 2; mi++) {
                int row_l = wm * 32 + mi * 16 + lg + po * 8;
                size_t hbase = (size_t)(m0 + row_l) * H2 + dir * H + nt * 32;
#pragma unroll
                for (int ni = 0; ni < 4; ni++) {
                    float s0 = po ? acc[mi][ni][0] : acc[mi][ni][2];
                    float s1 = po ? acc[mi][ni][1] : acc[mi][ni][3];
                    float r0 = __shfl_xor_sync(0xffffffffu, s0, 1);
                    float r1 = __shfl_xor_sync(0xffffffffu, s1, 1);
                    float gi, gf, gg, go;
                    if (po == 0) {
                        gi = acc[mi][ni][0] + bI[ni]; gf = acc[mi][ni][1] + bF[ni];
                        gg = r0 + bG[ni];             go = r1 + bO[ni];
                    } else {
                        gi = r0 + bI[ni];             gf = r1 + bF[ni];
                        gg = acc[mi][ni][2] + bG[ni]; go = acc[mi][ni][3] + bO[ni];
                    }
                    float c = cR[mi * 4 + ni];
                    float ct = fsigm(gf) * c + fsigm(gi) * ftanh(gg);
                    cR[mi * 4 + ni] = ct;
                    hout[hbase + uL[ni]] = __float2half(fsigm(go) * ftanh(ct));
                }
            }
            barrier_grp(gid, 16);
        }

        // flush c for decoder re-tiling
#pragma unroll
        for (int mi = 0; mi < 2; mi++) {
            int row_l = wm * 32 + mi * 16 + lg + po * 8;
#pragma unroll
            for (int ni = 0; ni < 4; ni++)
                g_c[(size_t)(m0 + row_l) * H2 + dir * H + nt * 32 + uL[ni]] = cR[mi * 4 + ni];
        }
        barrier_grp(12, NCTA);   // full transition barrier
    }

    // =============== decoder (R15 combined-stage schedule, register epilogue) ===============
    {
        int mt = bx >> 5, nt = bx & 31;
        int gid = 8 + mt;                  // 4 groups of 32 CTAs
        int m0 = mt * BM, n0 = nt * BN;
        const __half* W = g_Wdec + (size_t)n0 * KDEC;

        // prologue: W-parts of chunks 0/1 (h-independent)
        load_B(dynu + BOFF, W, KDEC, tid);
        CP_COMMIT();
        load_B(dynu + (uint32_t)STG_B + BOFF, W + KC, KDEC, tid);
        CP_COMMIT();

        float wI[4], wF[4], wG[4], wO[4];
#pragma unroll
        for (int ni = 0; ni < 4; ni++) {
            const float* bp = g_bdec + n0 + 4 * uL[ni];
            bI[ni] = bp[0]; bF[ni] = bp[1]; bG[ni] = bp[2]; bO[ni] = bp[3];
            const float* wp = g_win + n0 + 4 * uL[ni];
            wI[ni] = wp[0]; wF[ni] = wp[1]; wG[ni] = wp[2]; wO[ni] = wp[3];
        }
#pragma unroll
        for (int mi = 0; mi < 2; mi++) {
            int row_l = wm * 32 + mi * 16 + lg + po * 8;
#pragma unroll
            for (int ni = 0; ni < 4; ni++)
                cR[mi * 4 + ni] = ldcg(&g_c[(size_t)(m0 + row_l) * H2 + nt * 32 + uL[ni]]);
        }
        if (tid < 32) sFc[tid] = g_fcw[nt * 32 + tid];
        __syncthreads();

        int st0 = 0;
        for (int l = 0; l < L_OUT; l++) {
            int p = l & 1;
            const __half* hbase = g_h[p] + (size_t)m0 * H2;
            __half* hout = g_h[p ^ 1];

            load_A(dynu + (uint32_t)((st0 % 3) * STG_B), hbase, H2, tid, 1);
            CP_COMMIT();
            load_A(dynu + (uint32_t)(((st0 + 1) % 3) * STG_B), hbase + KC, H2, tid, 1);
            CP_COMMIT();

            // previous prediction partials (L1-bypass; barrier ordered)
            {
                int r = tid >> 2, q = tid & 3;
                float s = 0.0f;
                if (l > 0) {
                    const float* dp = g_dpart + (size_t)(l - 1) * 32 * B + m0 + r;
#pragma unroll
                    for (int j = 0; j < 8; j++) s += ldcg(dp + (q * 8 + j) * B);
                }
                predP[r][q] = s;
            }

            float acc[2][4][4];
#pragma unroll
            for (int a = 0; a < 2; a++)
#pragma unroll
                for (int bq = 0; bq < 4; bq++)
#pragma unroll
                    for (int cq = 0; cq < 4; cq++) acc[a][bq][cq] = 0.0f;

#pragma unroll
            for (int ch = 0; ch < 8; ch++) {
                if (ch == 7 && l + 1 >= L_OUT) { CP_WAIT0(); } else { CP_WAIT1(); }
                __syncthreads();
                int pf = ch + 2;
                if (pf <= 7) {
                    uint32_t su = dynu + (uint32_t)(((st0 + pf) % 3) * STG_B);
                    load_A(su, hbase + pf * KC, H2, tid, 1);
                    load_B(su + BOFF, W + pf * KC, KDEC, tid);
                } else if (pf == 8 && l + 1 < L_OUT) {
                    load_B(dynu + (uint32_t)(((st0 + 2) % 3) * STG_B) + BOFF, W, KDEC, tid);
                } else if (pf == 9 && l + 1 < L_OUT) {
                    load_B(dynu + (uint32_t)((st0 % 3) * STG_B) + BOFF, W + KC, KDEC, tid);
                }
                CP_COMMIT();
                uint32_t su2 = dynu + (uint32_t)(((st0 + ch) % 3) * STG_B);
                mma_chunk_lm(su2, su2 + BOFF, acc, bA0, bA1, bB0, bB1);
            }
            __syncthreads();

            if (tid < BM)
                predS[tid] = (l > 0)
                    ? (predP[tid][0] + predP[tid][1] + predP[tid][2] + predP[tid][3] + fcb0)
                    : 0.0f;
            __syncthreads();

            // register epilogue (+ Hs staging for fc partial)
#pragma unroll
            for (int mi = 0; mi < 2; mi++) {
                int row_l = wm * 32 + mi * 16 + lg + po * 8;
                float pb = predS[row_l];
                size_t hb2 = (size_t)(m0 + row_l) * H2 + nt * 32;
#pragma unroll
                for (int ni = 0; ni < 4; ni++) {
                    float s0 = po ? acc[mi][ni][0] : acc[mi][ni][2];
                    float s1 = po ? acc[mi][ni][1] : acc[mi][ni][3];
                    float r0 = __shfl_xor_sync(0xffffffffu, s0, 1);
                    float r1 = __shfl_xor_sync(0xffffffffu, s1, 1);
                    float gi, gf, gg, go;
                    if (po == 0) {
                        gi = acc[mi][ni][0] + bI[ni]; gf = acc[mi][ni][1] + bF[ni];
                        gg = r0 + bG[ni];             go = r1 + bO[ni];
                    } else {
                        gi = r0 + bI[ni];             gf = r1 + bF[ni];
                        gg = acc[mi][ni][2] + bG[ni]; go = acc[mi][ni][3] + bO[ni];
                    }
                    gi += pb * wI[ni]; gf += pb * wF[ni];
                    gg += pb * wG[ni]; go += pb * wO[ni];
                    float c = cR[mi * 4 + ni];
                    float ct = fsigm(gf) * c + fsigm(gi) * ftanh(gg);
                    cR[mi * 4 + ni] = ct;
                    float ht = fsigm(go) * ftanh(ct);
                    hout[hb2 + uL[ni]] = __float2half(ht);
                    Hs[row_l * HSP + uL[ni]] = ht;
                }
            }
            __syncthreads();
            if (tid < BM) {
                float s = 0.0f;
#pragma unroll
                for (int j = 0; j < 32; j++) s += sFc[j] * Hs[tid * HSP + j];
                g_dpart[(size_t)(l * 32 + nt) * B + m0 + tid] = s;
            }
            barrier_grp(gid, 32);
            st0 = (st0 + 2) % 3;
        }
    }

    // =============== finalize ===============
    barrier_grp(13, NCTA);
    {
        int idx = bx * 256 + tid;
        if (idx < B * L_OUT) {
            int b = idx / L_OUT, l = idx - b * L_OUT;
            float s = fcb0;
#pragma unroll
            for (int j = 0; j < 32; j++) s += ldcg(&g_dpart[(size_t)(l * 32 + j) * B + b]);
            out[idx] = s;
        }
    }
}

// ---------------- launch ----------------
extern "C" void kernel_launch(void* const* d_in, const int* in_sizes, int n_in,
                              void* d_out, int out_size) {
    const float* x      = (const float*)d_in[0];
    const float* eWih_f = (const float*)d_in[1];
    const float* eWhh_f = (const float*)d_in[2];
    const float* ebih_f = (const float*)d_in[3];
    const float* ebhh_f = (const float*)d_in[4];
    const float* eWih_b = (const float*)d_in[5];
    const float* eWhh_b = (const float*)d_in[6];
    const float* ebih_b = (const float*)d_in[7];
    const float* ebhh_b = (const float*)d_in[8];
    const float* dWih   = (const float*)d_in[9];
    const float* dWhh   = (const float*)d_in[10];
    const float* dbih   = (const float*)d_in[11];
    const float* dbhh   = (const float*)d_in[12];
    const float* fcW    = (const float*)d_in[13];
    const float* fcb    = (const float*)d_in[14];

    cudaFuncSetAttribute(persist, cudaFuncAttributeMaxDynamicSharedMemorySize, DYNB);

    prep_misc<<<(T * B * F_IN + 255) / 256, 256>>>(x);
    prep_w<<<(PREP_TOT + 255) / 256, 256>>>(eWih_f, eWhh_f, ebih_f, ebhh_f,
                                            eWih_b, eWhh_b, ebih_b, ebhh_b,
                                            dWih, dWhh, dbih, dbhh, fcW);
    persist<<<NCTA, 256, DYNB>>>((float*)d_out, fcb);
}